// round 12
// baseline (speedup 1.0000x reference)
#include <cuda_runtime.h>
#include <cuda_bf16.h>
#include <math.h>
#include <stdint.h>

#define D_MODEL 1024
#define NHEAD   16
#define DK      64
#define BATCH   4
#define SEQ     2048
#define M_ROWS  (BATCH*SEQ)   // 8192
#define HQKV    (BATCH*NHEAD*SEQ*DK)

// log2(e) folded constants
#define Q_PRESCALE 0.18033688011112042f   // 0.125 * log2(e)
#define CLIP_LOG2  72.13475204444817f     // 50 * log2(e)
#define MASKED_S   (-14427.0f)            // exp2 -> 0

// Inter-kernel interchange: bf16 hi/lo pairs (value = hi+lo, err ~2^-18 rel)
__device__ __align__(16) __nv_bfloat16 g_xhi[M_ROWS*D_MODEL];
__device__ __align__(16) __nv_bfloat16 g_xlo[M_ROWS*D_MODEL];
__device__ __align__(16) __nv_bfloat16 g_Whi[4*D_MODEL*D_MODEL];   // q,k,v,o
__device__ __align__(16) __nv_bfloat16 g_Wlo[4*D_MODEL*D_MODEL];
__device__ __align__(16) __nv_bfloat16 g_Qhi[HQKV];  // pre-scaled by 0.125*log2e
__device__ __align__(16) __nv_bfloat16 g_Qlo[HQKV];
__device__ __align__(16) __nv_bfloat16 g_Khi[HQKV];
__device__ __align__(16) __nv_bfloat16 g_Klo[HQKV];
__device__ __align__(16) __nv_bfloat16 g_Vhi[HQKV];
__device__ __align__(16) __nv_bfloat16 g_Vlo[HQKV];
__device__ __align__(16) __nv_bfloat16 g_ctxhi[M_ROWS*D_MODEL];
__device__ __align__(16) __nv_bfloat16 g_ctxlo[M_ROWS*D_MODEL];

// ---------------------------------------------------------------------------
__device__ __forceinline__ void ldmx4(uint32_t* r, uint32_t addr) {
    asm volatile("ldmatrix.sync.aligned.m8n8.x4.shared.b16 {%0,%1,%2,%3}, [%4];"
                 : "=r"(r[0]), "=r"(r[1]), "=r"(r[2]), "=r"(r[3]) : "r"(addr));
}
__device__ __forceinline__ void ldmx4t(uint32_t* r, uint32_t addr) {
    asm volatile("ldmatrix.sync.aligned.m8n8.x4.trans.shared.b16 {%0,%1,%2,%3}, [%4];"
                 : "=r"(r[0]), "=r"(r[1]), "=r"(r[2]), "=r"(r[3]) : "r"(addr));
}
__device__ __forceinline__ void mma_bf16(float* d, const uint32_t* a,
                                         uint32_t b0, uint32_t b1) {
    asm volatile(
        "mma.sync.aligned.m16n8k16.row.col.f32.bf16.bf16.f32 "
        "{%0,%1,%2,%3}, {%4,%5,%6,%7}, {%8,%9}, {%0,%1,%2,%3};"
        : "+f"(d[0]), "+f"(d[1]), "+f"(d[2]), "+f"(d[3])
        : "r"(a[0]), "r"(a[1]), "r"(a[2]), "r"(a[3]), "r"(b0), "r"(b1));
}
__device__ __forceinline__ uint32_t smem_u32(const void* p) {
    uint32_t a;
    asm("{ .reg .u64 t; cvta.to.shared.u64 t, %1; cvt.u32.u64 %0, t; }"
        : "=r"(a) : "l"(p));
    return a;
}
__device__ __forceinline__ void cp16(uint32_t saddr, const void* g) {
    asm volatile("cp.async.cg.shared.global [%0], [%1], 16;"
                 :: "r"(saddr), "l"(g) : "memory");
}
#define CP_COMMIT()   asm volatile("cp.async.commit_group;" ::: "memory")
#define CP_WAIT(n)    asm volatile("cp.async.wait_group %0;" :: "n"(n) : "memory")

__device__ __forceinline__ uint32_t sw128(uint32_t off) {
    return off ^ ((off >> 3) & 0x70);
}
__device__ __forceinline__ float ex2(float x) {
    float y;
    asm("ex2.approx.f32 %0, %1;" : "=f"(y) : "f"(x));
    return y;
}
__device__ __forceinline__ void split4(float4 v, uint2& H, uint2& L) {
    __nv_bfloat162 h0 = __floats2bfloat162_rn(v.x, v.y);
    __nv_bfloat162 h1 = __floats2bfloat162_rn(v.z, v.w);
    H.x = *reinterpret_cast<uint32_t*>(&h0);
    H.y = *reinterpret_cast<uint32_t*>(&h1);
    float rx = v.x - __uint_as_float(H.x << 16);
    float ry = v.y - __uint_as_float(H.x & 0xFFFF0000u);
    float rz = v.z - __uint_as_float(H.y << 16);
    float rw = v.w - __uint_as_float(H.y & 0xFFFF0000u);
    __nv_bfloat162 l0 = __floats2bfloat162_rn(rx, ry);
    __nv_bfloat162 l1 = __floats2bfloat162_rn(rz, rw);
    L.x = *reinterpret_cast<uint32_t*>(&l0);
    L.y = *reinterpret_cast<uint32_t*>(&l1);
}
__device__ __forceinline__ void split_pack2(float a, float b, uint32_t& H, uint32_t& L) {
    __nv_bfloat162 h2 = __floats2bfloat162_rn(a, b);
    H = *reinterpret_cast<uint32_t*>(&h2);
    float fa = __uint_as_float(H << 16);
    float fb = __uint_as_float(H & 0xFFFF0000u);
    __nv_bfloat162 l2 = __floats2bfloat162_rn(a - fa, b - fb);
    L = *reinterpret_cast<uint32_t*>(&l2);
}

// ---------------------------------------------------------------------------
// Pre-split kernels (memory-bound, one-shot)
// ---------------------------------------------------------------------------
__global__ __launch_bounds__(256) void split_x_kernel(const float* __restrict__ x) {
    const int i = blockIdx.x * 256 + threadIdx.x;
    float4 v = ((const float4*)x)[i];
    v.x += 1e-8f; v.y += 1e-8f; v.z += 1e-8f; v.w += 1e-8f;
    uint2 H, L;
    split4(v, H, L);
    ((uint2*)g_xhi)[i] = H;
    ((uint2*)g_xlo)[i] = L;
}

__global__ __launch_bounds__(256) void split_w_kernel(const float* __restrict__ W0,
                                                      const float* __restrict__ W1,
                                                      const float* __restrict__ W2,
                                                      const float* __restrict__ W3) {
    const int which = blockIdx.y;
    const float* W = which == 0 ? W0 : which == 1 ? W1 : which == 2 ? W2 : W3;
    const int i = blockIdx.x * 256 + threadIdx.x;
    float4 v = ((const float4*)W)[i];
    uint2 H, L;
    split4(v, H, L);
    const size_t o = (size_t)which * (D_MODEL*D_MODEL/4) + i;
    ((uint2*)g_Whi)[o] = H;
    ((uint2*)g_Wlo)[o] = L;
}

// ---------------------------------------------------------------------------
// HMMA GEMM v4: cp.async double-buffered, SINGLE sync per chunk
// (wait(0) -> sync -> prefetch next -> compute), 3-pass MMA ordering.
// ---------------------------------------------------------------------------
#define GEMM_BUF   49152
#define GEMM_SMEM  (2*GEMM_BUF)

template<bool QKV>
__global__ __launch_bounds__(256)
void hmma_gemm_kernel(const float* __restrict__ b0v,
                      const float* __restrict__ b1v,
                      const float* __restrict__ b2v,
                      float* __restrict__ outp)
{
    extern __shared__ __align__(1024) unsigned char gsm[];

    const int tid  = threadIdx.x;
    const int wid  = tid >> 5;
    const int lane = tid & 31;
    const int mw   = wid & 3;
    const int nw   = wid >> 2;

    const int bx    = blockIdx.x;
    const int which = QKV ? (bx >> 4) : 3;
    const int n0    = (bx & 15) * 64;
    const int m0    = blockIdx.y * 128;

    const __nv_bfloat16* Ahi = QKV ? g_xhi : g_ctxhi;
    const __nv_bfloat16* Alo = QKV ? g_xlo : g_ctxlo;
    const __nv_bfloat16* Whi = g_Whi + (size_t)which * D_MODEL * D_MODEL;
    const __nv_bfloat16* Wlo = g_Wlo + (size_t)which * D_MODEL * D_MODEL;
    const float* bias = QKV ? (which == 0 ? b0v : which == 1 ? b1v : b2v) : b0v;

    const uint32_t sb = smem_u32(gsm);

    const int blk      = lane >> 3;
    const int rr       = lane & 7;
    const int aRowHalf = blk & 1;
    const int aKHalf   = blk >> 1;
    const int bNb      = blk >> 1;
    const int bKHalf   = blk & 1;

    const int frow = tid >> 3;
    const int fcol = tid & 7;
    uint32_t swA[4], swB[2];
    #pragma unroll
    for (int i = 0; i < 4; i++)
        swA[i] = sw128((uint32_t)((frow + i*32) * 128 + fcol * 16));
    swB[0] = swA[0];
    swB[1] = swA[1];

    float acc[2][4][4];
    #pragma unroll
    for (int i=0;i<2;i++)
        #pragma unroll
        for (int j=0;j<4;j++)
            #pragma unroll
            for (int l=0;l<4;l++) acc[i][j][l]=0.f;

    // Prologue: async-load chunk 0 into buffer 0
    {
        #pragma unroll
        for (int i = 0; i < 4; i++) {
            const size_t go = (size_t)(m0 + frow + i*32) * D_MODEL + fcol * 8;
            cp16(sb + swA[i],         Ahi + go);
            cp16(sb + 16384 + swA[i], Alo + go);
        }
        #pragma unroll
        for (int i = 0; i < 2; i++) {
            const size_t go = (size_t)(n0 + frow + i*32) * D_MODEL + fcol * 8;
            cp16(sb + 32768 + swB[i], Whi + go);
            cp16(sb + 40960 + swB[i], Wlo + go);
        }
        CP_COMMIT();
    }

    for (int chunk = 0; chunk < 16; chunk++) {
        const uint32_t cbuf = (uint32_t)(chunk & 1) * GEMM_BUF;

        CP_WAIT(0);          // own chunk-`chunk` loads complete
        __syncthreads();     // everyone's loads visible + compute(chunk-1) done

        if (chunk + 1 < 16) {
            const uint32_t nbuf = (uint32_t)((chunk + 1) & 1) * GEMM_BUF;
            const int k1 = (chunk + 1) * 64;
            #pragma unroll
            for (int i = 0; i < 4; i++) {
                const size_t go = (size_t)(m0 + frow + i*32) * D_MODEL + k1 + fcol * 8;
                cp16(sb + nbuf + swA[i],         Ahi + go);
                cp16(sb + nbuf + 16384 + swA[i], Alo + go);
            }
            #pragma unroll
            for (int i = 0; i < 2; i++) {
                const size_t go = (size_t)(n0 + frow + i*32) * D_MODEL + k1 + fcol * 8;
                cp16(sb + nbuf + 32768 + swB[i], Whi + go);
                cp16(sb + nbuf + 40960 + swB[i], Wlo + go);
            }
            CP_COMMIT();
        }

        #pragma unroll
        for (int ks = 0; ks < 4; ks++) {
            uint32_t ah[2][4], al[2][4];
            #pragma unroll
            for (int mf = 0; mf < 2; mf++) {
                const uint32_t row = (uint32_t)(mw*32 + mf*16 + aRowHalf*8 + rr);
                const uint32_t off = sw128(row * 128 + (uint32_t)(ks*16 + aKHalf*8) * 2);
                ldmx4(ah[mf], sb + cbuf + off);
                ldmx4(al[mf], sb + cbuf + 16384 + off);
            }
            uint32_t bh[2][4], bl[2][4];
            #pragma unroll
            for (int pr = 0; pr < 2; pr++) {
                const uint32_t n   = (uint32_t)(nw*32 + pr*16 + bNb*8 + rr);
                const uint32_t off = sw128(n * 128 + (uint32_t)(ks*16 + bKHalf*8) * 2);
                ldmx4(bh[pr], sb + cbuf + 32768 + off);
                ldmx4(bl[pr], sb + cbuf + 40960 + off);
            }
            #pragma unroll
            for (int mf = 0; mf < 2; mf++)
                #pragma unroll
                for (int nb = 0; nb < 4; nb++)
                    mma_bf16(acc[mf][nb], ah[mf], bh[nb>>1][(nb&1)*2], bh[nb>>1][(nb&1)*2+1]);
            #pragma unroll
            for (int mf = 0; mf < 2; mf++)
                #pragma unroll
                for (int nb = 0; nb < 4; nb++)
                    mma_bf16(acc[mf][nb], ah[mf], bl[nb>>1][(nb&1)*2], bl[nb>>1][(nb&1)*2+1]);
            #pragma unroll
            for (int mf = 0; mf < 2; mf++)
                #pragma unroll
                for (int nb = 0; nb < 4; nb++)
                    mma_bf16(acc[mf][nb], al[mf], bh[nb>>1][(nb&1)*2], bh[nb>>1][(nb&1)*2+1]);
        }
    }

    const int gID = lane >> 2;
    const int tg  = lane & 3;

    #pragma unroll
    for (int mf = 0; mf < 2; mf++) {
        #pragma unroll
        for (int nb = 0; nb < 4; nb++) {
            const int colL = nw*32 + nb*8 + tg*2;
            const float bb0 = bias[n0 + colL];
            const float bb1 = bias[n0 + colL + 1];
            #pragma unroll
            for (int half = 0; half < 2; half++) {
                const int m = m0 + mw*32 + mf*16 + half*8 + gID;
                if (QKV && which < 3) {
                    float v0 = fminf(fmaxf(acc[mf][nb][half*2+0] + bb0, -10.f), 10.f);
                    float v1 = fminf(fmaxf(acc[mf][nb][half*2+1] + bb1, -10.f), 10.f);
                    if (which == 0) { v0 *= Q_PRESCALE; v1 *= Q_PRESCALE; }
                    uint32_t H, L;
                    split_pack2(v0, v1, H, L);
                    const int b_ = m >> 11;
                    const int t  = m & (SEQ - 1);
                    const int h  = bx & 15;
                    const size_t o = (((size_t)(b_*NHEAD + h))*SEQ + t)*DK + colL;
                    __nv_bfloat16* dh = (which == 0) ? g_Qhi : (which == 1) ? g_Khi : g_Vhi;
                    __nv_bfloat16* dl = (which == 0) ? g_Qlo : (which == 1) ? g_Klo : g_Vlo;
                    *(uint32_t*)(dh + o) = H;
                    *(uint32_t*)(dl + o) = L;
                } else {
                    float2 v;
                    v.x = fminf(fmaxf(acc[mf][nb][half*2+0] + bb0, -100.f), 100.f);
                    v.y = fminf(fmaxf(acc[mf][nb][half*2+1] + bb1, -100.f), 100.f);
                    *(float2*)(outp + (size_t)m * D_MODEL + n0 + colL) = v;
                }
            }
        }
    }
}

// ---------------------------------------------------------------------------
// HMMA flash attention v6: 128-thread CTAs (2/SM), SINGLE sync per tile
// (wait(0) -> sync -> prefetch -> compute), smask ping-pong, deferred
// row-sum reduction (per-lane partials, shuffle once after the loop).
// ---------------------------------------------------------------------------
#define ATTN_SMEM 65536
#define NT (SEQ/64)

__global__ __launch_bounds__(128, 2)
void attn_hmma_kernel(const unsigned char* __restrict__ mask)
{
    extern __shared__ __align__(1024) unsigned char sbuf[];
    __shared__ uint32_t smask2[2][16];

    const int tid  = threadIdx.x;
    const int wid  = tid >> 5;          // 0..3
    const int lane = tid & 31;
    const int gID  = lane >> 2;
    const int tg   = lane & 3;

    const int blk      = lane >> 3;
    const int rr       = lane & 7;
    const int aRowHalf = blk & 1;
    const int aKHalf   = blk >> 1;
    const int bNb      = blk >> 1;
    const int bKHalf   = blk & 1;

    const int vKey = lane & 15;
    const int vDh  = lane >> 4;

    const int qt = blockIdx.x;          // 0..31
    const int h  = blockIdx.y;
    const int b  = blockIdx.z;
    const int m0 = qt * 64;

    const size_t headoff = ((size_t)(b*NHEAD + h))*SEQ*DK;
    const __nv_bfloat16* Qhi = g_Qhi + headoff;
    const __nv_bfloat16* Qlo = g_Qlo + headoff;
    const __nv_bfloat16* Khi = g_Khi + headoff;
    const __nv_bfloat16* Klo = g_Klo + headoff;
    const __nv_bfloat16* Vhi = g_Vhi + headoff;
    const __nv_bfloat16* Vlo = g_Vlo + headoff;
    const unsigned char* mb = mask + (size_t)b*SEQ;

    const uint32_t sb = smem_u32(sbuf);

    const int frow = tid >> 3;          // 0..15
    const int fcol = tid & 7;           // 0..7
    uint32_t swf[4];
    #pragma unroll
    for (int i = 0; i < 4; i++)
        swf[i] = sw128((uint32_t)((frow + i*16) * 128 + fcol * 16));

    // ---- Phase 0: Q tile 64x64 bf16 (pre-scaled) -> smem -> registers
    #pragma unroll
    for (int i = 0; i < 4; i++) {
        const int f   = tid + i * 128;
        const int row = f >> 3;
        const int c   = f & 7;
        const size_t go = (size_t)(m0 + row) * DK + c * 8;
        const uint32_t sw = sw128((uint32_t)(row * 128 + c * 16));
        *(uint4*)(sbuf + sw)        = *(const uint4*)(Qhi + go);
        *(uint4*)(sbuf + 8192 + sw) = *(const uint4*)(Qlo + go);
    }
    __syncthreads();

    uint32_t qh[4][4], ql[4][4];
    #pragma unroll
    for (int ks = 0; ks < 4; ks++) {
        const uint32_t row = (uint32_t)(wid*16 + aRowHalf*8 + rr);
        const uint32_t off = sw128(row * 128 + (uint32_t)(ks*16 + aKHalf*8) * 2);
        ldmx4(qh[ks], sb + off);
        ldmx4(ql[ks], sb + 8192 + off);
    }
    __syncthreads();   // Q smem dead; overlay with K/V buffers

    float oacc[8][4];
    #pragma unroll
    for (int nb = 0; nb < 8; nb++)
        #pragma unroll
        for (int i = 0; i < 4; i++) oacc[nb][i] = 0.f;
    float lrun0 = 0.f, lrun1 = 0.f;   // per-lane partials; reduced after loop

    // ---- prologue: async-load tile 0 + mask slot 0
    {
        #pragma unroll
        for (int i = 0; i < 4; i++) {
            const size_t g = (size_t)(frow + i*16) * DK + fcol * 8;
            cp16(sb + swf[i],         Khi + g);
            cp16(sb +  8192 + swf[i], Klo + g);
            cp16(sb + 16384 + swf[i], Vhi + g);
            cp16(sb + 24576 + swf[i], Vlo + g);
        }
        CP_COMMIT();
        if (tid < 16) smask2[0][tid] = *(const uint32_t*)(mb + tid*4);
    }

    for (int t = 0; t < NT; t++) {
        const int kt = t * 64;
        const uint32_t cbuf = (uint32_t)(t & 1) * 32768;

        CP_WAIT(0);          // own tile-t loads complete
        __syncthreads();     // everyone's loads visible + compute(t-1) done

        if (t + 1 < NT) {
            const uint32_t nbuf = (uint32_t)((t + 1) & 1) * 32768;
            const size_t base = (size_t)(kt + 64) * DK;
            #pragma unroll
            for (int i = 0; i < 4; i++) {
                const size_t g = base + (size_t)(frow + i*16) * DK + fcol * 8;
                cp16(sb + nbuf + swf[i],         Khi + g);
                cp16(sb + nbuf +  8192 + swf[i], Klo + g);
                cp16(sb + nbuf + 16384 + swf[i], Vhi + g);
                cp16(sb + nbuf + 24576 + swf[i], Vlo + g);
            }
            CP_COMMIT();
            if (tid < 16) smask2[(t+1)&1][tid] = *(const uint32_t*)(mb + kt + 64 + tid*4);
        }

        const unsigned char* smk = (const unsigned char*)smask2[t & 1];

        // ---- QK^T: per ks, batch B-fragments then 3 MMA passes (dist 8)
        float sacc[8][4];
        #pragma unroll
        for (int nt = 0; nt < 8; nt++)
            #pragma unroll
            for (int i = 0; i < 4; i++) sacc[nt][i] = 0.f;

        #pragma unroll
        for (int ks = 0; ks < 4; ks++) {
            uint32_t bh[4][4], bl[4][4];
            #pragma unroll
            for (int kg = 0; kg < 4; kg++) {
                const uint32_t row = (uint32_t)(kg*16 + bNb*8 + rr);
                const uint32_t off = sw128(row * 128 + (uint32_t)(ks*16 + bKHalf*8) * 2);
                ldmx4(bh[kg], sb + cbuf + off);
                ldmx4(bl[kg], sb + cbuf + 8192 + off);
            }
            #pragma unroll
            for (int kg = 0; kg < 4; kg++)
                #pragma unroll
                for (int sub = 0; sub < 2; sub++)
                    mma_bf16(sacc[kg*2+sub], qh[ks], bh[kg][sub*2], bh[kg][sub*2+1]);
            #pragma unroll
            for (int kg = 0; kg < 4; kg++)
                #pragma unroll
                for (int sub = 0; sub < 2; sub++)
                    mma_bf16(sacc[kg*2+sub], qh[ks], bl[kg][sub*2], bl[kg][sub*2+1]);
            #pragma unroll
            for (int kg = 0; kg < 4; kg++)
                #pragma unroll
                for (int sub = 0; sub < 2; sub++)
                    mma_bf16(sacc[kg*2+sub], ql[ks], bh[kg][sub*2], bh[kg][sub*2+1]);
        }

        // ---- clip (log2 domain), mask, p=exp2(s), pack PV fragments
        uint32_t pah[4][4], pal[4][4];
        #pragma unroll
        for (int nt = 0; nt < 8; nt++) {
            const int keyc = nt*8 + tg*2;
            const bool f0 = smk[keyc] != 0;
            const bool f1 = smk[keyc + 1] != 0;
            float s0 = fminf(fmaxf(sacc[nt][0], -CLIP_LOG2), CLIP_LOG2); if (f0) s0 = MASKED_S;
            float s1 = fminf(fmaxf(sacc[nt][1], -CLIP_LOG2), CLIP_LOG2); if (f1) s1 = MASKED_S;
            float s2 = fminf(fmaxf(sacc[nt][2], -CLIP_LOG2), CLIP_LOG2); if (f0) s2 = MASKED_S;
            float s3 = fminf(fmaxf(sacc[nt][3], -CLIP_LOG2), CLIP_LOG2); if (f1) s3 = MASKED_S;
            const float p0 = ex2(s0);
            const float p1 = ex2(s1);
            const float p2 = ex2(s2);
            const float p3 = ex2(s3);
            lrun0 += p0 + p1;
            lrun1 += p2 + p3;
            const int ks  = nt >> 1;
            const int sub = nt & 1;
            split_pack2(p0, p1, pah[ks][sub*2+0], pal[ks][sub*2+0]);
            split_pack2(p2, p3, pah[ks][sub*2+1], pal[ks][sub*2+1]);
        }

        // ---- PV: per ks, batch V-fragments then 3 MMA passes (dist 8)
        #pragma unroll
        for (int ks = 0; ks < 4; ks++) {
            uint32_t vh[4][4], vl[4][4];
            #pragma unroll
            for (int dg = 0; dg < 4; dg++) {
                const uint32_t key = (uint32_t)(ks*16 + vKey);
                const uint32_t off = sw128(key * 128 + (uint32_t)(dg*16 + vDh*8) * 2);
                ldmx4t(vh[dg], sb + cbuf + 16384 + off);
                ldmx4t(vl[dg], sb + cbuf + 24576 + off);
            }
            #pragma unroll
            for (int dg = 0; dg < 4; dg++)
                #pragma unroll
                for (int sub = 0; sub < 2; sub++)
                    mma_bf16(oacc[dg*2+sub], pah[ks], vh[dg][sub*2], vh[dg][sub*2+1]);
            #pragma unroll
            for (int dg = 0; dg < 4; dg++)
                #pragma unroll
                for (int sub = 0; sub < 2; sub++)
                    mma_bf16(oacc[dg*2+sub], pah[ks], vl[dg][sub*2], vl[dg][sub*2+1]);
            #pragma unroll
            for (int dg = 0; dg < 4; dg++)
                #pragma unroll
                for (int sub = 0; sub < 2; sub++)
                    mma_bf16(oacc[dg*2+sub], pal[ks], vh[dg][sub*2], vh[dg][sub*2+1]);
        }
    }

    // ---- deferred row-sum reduction (once, after all tiles)
    lrun0 += __shfl_xor_sync(0xffffffffu, lrun0, 1);
    lrun0 += __shfl_xor_sync(0xffffffffu, lrun0, 2);
    lrun1 += __shfl_xor_sync(0xffffffffu, lrun1, 1);
    lrun1 += __shfl_xor_sync(0xffffffffu, lrun1, 2);

    const float inv0 = 1.f / lrun0;
    const float inv1 = 1.f / lrun1;
    const int row0 = m0 + wid*16 + gID;
    const int row1 = row0 + 8;
    const size_t o0 = ((size_t)(b*SEQ + row0))*D_MODEL + h*DK;
    const size_t o1 = ((size_t)(b*SEQ + row1))*D_MODEL + h*DK;
    #pragma unroll
    for (int nb = 0; nb < 8; nb++) {
        const int col = nb*8 + tg*2;
        uint32_t H, L;
        split_pack2(oacc[nb][0]*inv0, oacc[nb][1]*inv0, H, L);
        *(uint32_t*)(g_ctxhi + o0 + col) = H;
        *(uint32_t*)(g_ctxlo + o0 + col) = L;
        split_pack2(oacc[nb][2]*inv1, oacc[nb][3]*inv1, H, L);
        *(uint32_t*)(g_ctxhi + o1 + col) = H;
        *(uint32_t*)(g_ctxlo + o1 + col) = L;
    }
}

// ---------------------------------------------------------------------------
extern "C" void kernel_launch(void* const* d_in, const int* in_sizes, int n_in,
                              void* d_out, int out_size)
{
    const float* x  = (const float*)d_in[0];
    const unsigned char* mask = (const unsigned char*)d_in[1];
    const float* Wq = (const float*)d_in[2];
    const float* bq = (const float*)d_in[3];
    const float* Wk = (const float*)d_in[4];
    const float* bk = (const float*)d_in[5];
    const float* Wv = (const float*)d_in[6];
    const float* bv = (const float*)d_in[7];
    const float* Wo = (const float*)d_in[8];
    const float* bo = (const float*)d_in[9];
    float* out = (float*)d_out;

    cudaFuncSetAttribute(attn_hmma_kernel,
                         cudaFuncAttributeMaxDynamicSharedMemorySize, ATTN_SMEM);
    cudaFuncSetAttribute(hmma_gemm_kernel<true>,
                         cudaFuncAttributeMaxDynamicSharedMemorySize, GEMM_SMEM);
    cudaFuncSetAttribute(hmma_gemm_kernel<false>,
                         cudaFuncAttributeMaxDynamicSharedMemorySize, GEMM_SMEM);

    split_x_kernel<<<M_ROWS*D_MODEL/4/256, 256>>>(x);
    split_w_kernel<<<dim3(D_MODEL*D_MODEL/4/256, 4), 256>>>(Wq, Wk, Wv, Wo);

    hmma_gemm_kernel<true><<<dim3(48, M_ROWS/128), 256, GEMM_SMEM>>>(bq, bk, bv, nullptr);

    attn_hmma_kernel<<<dim3(SEQ/64, NHEAD, BATCH), 128, ATTN_SMEM>>>(mask);

    hmma_gemm_kernel<false><<<dim3(16, M_ROWS/128), 256, GEMM_SMEM>>>(bo, bo, bo, out);
}

// round 14
// speedup vs baseline: 1.0132x; 1.0132x over previous
#include <cuda_runtime.h>
#include <cuda_bf16.h>
#include <math.h>
#include <stdint.h>

#define D_MODEL 1024
#define NHEAD   16
#define DK      64
#define BATCH   4
#define SEQ     2048
#define M_ROWS  (BATCH*SEQ)   // 8192
#define HQKV    (BATCH*NHEAD*SEQ*DK)

// log2(e) folded constants
#define Q_PRESCALE 0.18033688011112042f   // 0.125 * log2(e)
#define CLIP_LOG2  72.13475204444817f     // 50 * log2(e)
#define MASKED_S   (-14427.0f)            // exp2 -> 0

// Inter-kernel interchange: bf16 hi/lo pairs (value = hi+lo, err ~2^-18 rel)
__device__ __align__(16) __nv_bfloat16 g_xhi[M_ROWS*D_MODEL];
__device__ __align__(16) __nv_bfloat16 g_xlo[M_ROWS*D_MODEL];
__device__ __align__(16) __nv_bfloat16 g_Whi[4*D_MODEL*D_MODEL];   // q,k,v,o
__device__ __align__(16) __nv_bfloat16 g_Wlo[4*D_MODEL*D_MODEL];
__device__ __align__(16) __nv_bfloat16 g_Qhi[HQKV];  // pre-scaled by 0.125*log2e
__device__ __align__(16) __nv_bfloat16 g_Qlo[HQKV];
__device__ __align__(16) __nv_bfloat16 g_Khi[HQKV];
__device__ __align__(16) __nv_bfloat16 g_Klo[HQKV];
__device__ __align__(16) __nv_bfloat16 g_Vhi[HQKV];
__device__ __align__(16) __nv_bfloat16 g_Vlo[HQKV];
__device__ __align__(16) __nv_bfloat16 g_ctxhi[M_ROWS*D_MODEL];
__device__ __align__(16) __nv_bfloat16 g_ctxlo[M_ROWS*D_MODEL];

// ---------------------------------------------------------------------------
__device__ __forceinline__ void ldmx4(uint32_t* r, uint32_t addr) {
    asm volatile("ldmatrix.sync.aligned.m8n8.x4.shared.b16 {%0,%1,%2,%3}, [%4];"
                 : "=r"(r[0]), "=r"(r[1]), "=r"(r[2]), "=r"(r[3]) : "r"(addr));
}
__device__ __forceinline__ void ldmx4t(uint32_t* r, uint32_t addr) {
    asm volatile("ldmatrix.sync.aligned.m8n8.x4.trans.shared.b16 {%0,%1,%2,%3}, [%4];"
                 : "=r"(r[0]), "=r"(r[1]), "=r"(r[2]), "=r"(r[3]) : "r"(addr));
}
__device__ __forceinline__ void mma_bf16(float* d, const uint32_t* a,
                                         uint32_t b0, uint32_t b1) {
    asm volatile(
        "mma.sync.aligned.m16n8k16.row.col.f32.bf16.bf16.f32 "
        "{%0,%1,%2,%3}, {%4,%5,%6,%7}, {%8,%9}, {%0,%1,%2,%3};"
        : "+f"(d[0]), "+f"(d[1]), "+f"(d[2]), "+f"(d[3])
        : "r"(a[0]), "r"(a[1]), "r"(a[2]), "r"(a[3]), "r"(b0), "r"(b1));
}
__device__ __forceinline__ uint32_t smem_u32(const void* p) {
    uint32_t a;
    asm("{ .reg .u64 t; cvta.to.shared.u64 t, %1; cvt.u32.u64 %0, t; }"
        : "=r"(a) : "l"(p));
    return a;
}
__device__ __forceinline__ void cp16(uint32_t saddr, const void* g) {
    asm volatile("cp.async.cg.shared.global [%0], [%1], 16;"
                 :: "r"(saddr), "l"(g) : "memory");
}
#define CP_COMMIT()   asm volatile("cp.async.commit_group;" ::: "memory")
#define CP_WAIT(n)    asm volatile("cp.async.wait_group %0;" :: "n"(n) : "memory")

__device__ __forceinline__ uint32_t sw128(uint32_t off) {
    return off ^ ((off >> 3) & 0x70);
}
__device__ __forceinline__ float ex2(float x) {
    float y;
    asm("ex2.approx.f32 %0, %1;" : "=f"(y) : "f"(x));
    return y;
}
__device__ __forceinline__ void split4(float4 v, uint2& H, uint2& L) {
    __nv_bfloat162 h0 = __floats2bfloat162_rn(v.x, v.y);
    __nv_bfloat162 h1 = __floats2bfloat162_rn(v.z, v.w);
    H.x = *reinterpret_cast<uint32_t*>(&h0);
    H.y = *reinterpret_cast<uint32_t*>(&h1);
    float rx = v.x - __uint_as_float(H.x << 16);
    float ry = v.y - __uint_as_float(H.x & 0xFFFF0000u);
    float rz = v.z - __uint_as_float(H.y << 16);
    float rw = v.w - __uint_as_float(H.y & 0xFFFF0000u);
    __nv_bfloat162 l0 = __floats2bfloat162_rn(rx, ry);
    __nv_bfloat162 l1 = __floats2bfloat162_rn(rz, rw);
    L.x = *reinterpret_cast<uint32_t*>(&l0);
    L.y = *reinterpret_cast<uint32_t*>(&l1);
}
__device__ __forceinline__ void split_pack2(float a, float b, uint32_t& H, uint32_t& L) {
    __nv_bfloat162 h2 = __floats2bfloat162_rn(a, b);
    H = *reinterpret_cast<uint32_t*>(&h2);
    float fa = __uint_as_float(H << 16);
    float fb = __uint_as_float(H & 0xFFFF0000u);
    __nv_bfloat162 l2 = __floats2bfloat162_rn(a - fa, b - fb);
    L = *reinterpret_cast<uint32_t*>(&l2);
}

// ---------------------------------------------------------------------------
// Pre-split kernels (memory-bound, one-shot)
// ---------------------------------------------------------------------------
__global__ __launch_bounds__(256) void split_x_kernel(const float* __restrict__ x) {
    const int i = blockIdx.x * 256 + threadIdx.x;
    float4 v = ((const float4*)x)[i];
    v.x += 1e-8f; v.y += 1e-8f; v.z += 1e-8f; v.w += 1e-8f;
    uint2 H, L;
    split4(v, H, L);
    ((uint2*)g_xhi)[i] = H;
    ((uint2*)g_xlo)[i] = L;
}

__global__ __launch_bounds__(256) void split_w_kernel(const float* __restrict__ W0,
                                                      const float* __restrict__ W1,
                                                      const float* __restrict__ W2,
                                                      const float* __restrict__ W3) {
    const int which = blockIdx.y;
    const float* W = which == 0 ? W0 : which == 1 ? W1 : which == 2 ? W2 : W3;
    const int i = blockIdx.x * 256 + threadIdx.x;
    float4 v = ((const float4*)W)[i];
    uint2 H, L;
    split4(v, H, L);
    const size_t o = (size_t)which * (D_MODEL*D_MODEL/4) + i;
    ((uint2*)g_Whi)[o] = H;
    ((uint2*)g_Wlo)[o] = L;
}

// ---------------------------------------------------------------------------
// HMMA GEMM v5: 64x64 CTA tile, 128 threads, 3 CTAs/SM. cp.async double-
// buffered (prefetch-before-wait), 3-pass MMA.
// smem/buffer 32KB: Ahi@0(8K) Alo@8K Bhi@16K Blo@24K; x2 = 64KB.
// ---------------------------------------------------------------------------
#define GEMM_BUF   32768
#define GEMM_SMEM  (2*GEMM_BUF)

template<bool QKV>
__global__ __launch_bounds__(128, 3)
void hmma_gemm_kernel(const float* __restrict__ b0v,
                      const float* __restrict__ b1v,
                      const float* __restrict__ b2v,
                      float* __restrict__ outp)
{
    extern __shared__ __align__(1024) unsigned char gsm[];

    const int tid  = threadIdx.x;
    const int wid  = tid >> 5;          // 0..3
    const int lane = tid & 31;
    const int mw   = wid >> 1;          // 0..1
    const int nw   = wid & 1;           // 0..1

    const int bx    = blockIdx.x;
    const int which = QKV ? (bx >> 4) : 3;
    const int n0    = (bx & 15) * 64;
    const int m0    = blockIdx.y * 64;

    const __nv_bfloat16* Ahi = QKV ? g_xhi : g_ctxhi;
    const __nv_bfloat16* Alo = QKV ? g_xlo : g_ctxlo;
    const __nv_bfloat16* Whi = g_Whi + (size_t)which * D_MODEL * D_MODEL;
    const __nv_bfloat16* Wlo = g_Wlo + (size_t)which * D_MODEL * D_MODEL;
    const float* bias = QKV ? (which == 0 ? b0v : which == 1 ? b1v : b2v) : b0v;

    const uint32_t sb = smem_u32(gsm);

    const int blk      = lane >> 3;
    const int rr       = lane & 7;
    const int aRowHalf = blk & 1;
    const int aKHalf   = blk >> 1;
    const int bNb      = blk >> 1;
    const int bKHalf   = blk & 1;

    const int frow = tid >> 3;          // 0..15
    const int fcol = tid & 7;           // 0..7
    uint32_t swf[4];
    #pragma unroll
    for (int i = 0; i < 4; i++)
        swf[i] = sw128((uint32_t)((frow + i*16) * 128 + fcol * 16));

    float acc[2][4][4];
    #pragma unroll
    for (int i=0;i<2;i++)
        #pragma unroll
        for (int j=0;j<4;j++)
            #pragma unroll
            for (int l=0;l<4;l++) acc[i][j][l]=0.f;

    // Prologue: async-load chunk 0 into buffer 0
    {
        #pragma unroll
        for (int i = 0; i < 4; i++) {
            const size_t ga = (size_t)(m0 + frow + i*16) * D_MODEL + fcol * 8;
            const size_t gb = (size_t)(n0 + frow + i*16) * D_MODEL + fcol * 8;
            cp16(sb + swf[i],         Ahi + ga);
            cp16(sb +  8192 + swf[i], Alo + ga);
            cp16(sb + 16384 + swf[i], Whi + gb);
            cp16(sb + 24576 + swf[i], Wlo + gb);
        }
        CP_COMMIT();
    }

    for (int chunk = 0; chunk < 16; chunk++) {
        const uint32_t cbuf = (uint32_t)(chunk & 1) * GEMM_BUF;

        if (chunk + 1 < 16) {
            const uint32_t nbuf = (uint32_t)((chunk + 1) & 1) * GEMM_BUF;
            const int k1 = (chunk + 1) * 64;
            #pragma unroll
            for (int i = 0; i < 4; i++) {
                const size_t ga = (size_t)(m0 + frow + i*16) * D_MODEL + k1 + fcol * 8;
                const size_t gb = (size_t)(n0 + frow + i*16) * D_MODEL + k1 + fcol * 8;
                cp16(sb + nbuf + swf[i],         Ahi + ga);
                cp16(sb + nbuf +  8192 + swf[i], Alo + ga);
                cp16(sb + nbuf + 16384 + swf[i], Whi + gb);
                cp16(sb + nbuf + 24576 + swf[i], Wlo + gb);
            }
            CP_COMMIT();
            CP_WAIT(1);
        } else {
            CP_WAIT(0);
        }
        __syncthreads();

        #pragma unroll
        for (int ks = 0; ks < 4; ks++) {
            uint32_t ah[2][4], al[2][4];
            #pragma unroll
            for (int mf = 0; mf < 2; mf++) {
                const uint32_t row = (uint32_t)(mw*32 + mf*16 + aRowHalf*8 + rr);
                const uint32_t off = sw128(row * 128 + (uint32_t)(ks*16 + aKHalf*8) * 2);
                ldmx4(ah[mf], sb + cbuf + off);
                ldmx4(al[mf], sb + cbuf + 8192 + off);
            }
            uint32_t bh[2][4], bl[2][4];
            #pragma unroll
            for (int pr = 0; pr < 2; pr++) {
                const uint32_t n   = (uint32_t)(nw*32 + pr*16 + bNb*8 + rr);
                const uint32_t off = sw128(n * 128 + (uint32_t)(ks*16 + bKHalf*8) * 2);
                ldmx4(bh[pr], sb + cbuf + 16384 + off);
                ldmx4(bl[pr], sb + cbuf + 24576 + off);
            }
            #pragma unroll
            for (int mf = 0; mf < 2; mf++)
                #pragma unroll
                for (int nb = 0; nb < 4; nb++)
                    mma_bf16(acc[mf][nb], ah[mf], bh[nb>>1][(nb&1)*2], bh[nb>>1][(nb&1)*2+1]);
            #pragma unroll
            for (int mf = 0; mf < 2; mf++)
                #pragma unroll
                for (int nb = 0; nb < 4; nb++)
                    mma_bf16(acc[mf][nb], ah[mf], bl[nb>>1][(nb&1)*2], bl[nb>>1][(nb&1)*2+1]);
            #pragma unroll
            for (int mf = 0; mf < 2; mf++)
                #pragma unroll
                for (int nb = 0; nb < 4; nb++)
                    mma_bf16(acc[mf][nb], al[mf], bh[nb>>1][(nb&1)*2], bh[nb>>1][(nb&1)*2+1]);
        }
        __syncthreads();   // buffer consumed before chunk+2 overwrites it
    }

    const int gID = lane >> 2;
    const int tg  = lane & 3;

    #pragma unroll
    for (int mf = 0; mf < 2; mf++) {
        #pragma unroll
        for (int nb = 0; nb < 4; nb++) {
            const int colL = nw*32 + nb*8 + tg*2;
            const float bb0 = bias[n0 + colL];
            const float bb1 = bias[n0 + colL + 1];
            #pragma unroll
            for (int half = 0; half < 2; half++) {
                const int m = m0 + mw*32 + mf*16 + half*8 + gID;
                if (QKV && which < 3) {
                    float v0 = fminf(fmaxf(acc[mf][nb][half*2+0] + bb0, -10.f), 10.f);
                    float v1 = fminf(fmaxf(acc[mf][nb][half*2+1] + bb1, -10.f), 10.f);
                    if (which == 0) { v0 *= Q_PRESCALE; v1 *= Q_PRESCALE; }
                    uint32_t H, L;
                    split_pack2(v0, v1, H, L);
                    const int b_ = m >> 11;
                    const int t  = m & (SEQ - 1);
                    const int h  = bx & 15;
                    const size_t o = (((size_t)(b_*NHEAD + h))*SEQ + t)*DK + colL;
                    __nv_bfloat16* dh = (which == 0) ? g_Qhi : (which == 1) ? g_Khi : g_Vhi;
                    __nv_bfloat16* dl = (which == 0) ? g_Qlo : (which == 1) ? g_Klo : g_Vlo;
                    *(uint32_t*)(dh + o) = H;
                    *(uint32_t*)(dl + o) = L;
                } else {
                    float2 v;
                    v.x = fminf(fmaxf(acc[mf][nb][half*2+0] + bb0, -100.f), 100.f);
                    v.y = fminf(fmaxf(acc[mf][nb][half*2+1] + bb1, -100.f), 100.f);
                    *(float2*)(outp + (size_t)m * D_MODEL + n0 + colL) = v;
                }
            }
        }
    }
}

// ---------------------------------------------------------------------------
// HMMA flash attention v8: R11 pipeline (prefetch-before-wait), ping-pong
// smask, deferred row-sum reduction, FULL 3-pass split-bf16 PV (the P-lo
// plane is precision-mandatory: measured 1.6e-3 without it).
// ---------------------------------------------------------------------------
#define ATTN_SMEM 65536
#define NT (SEQ/64)

__global__ __launch_bounds__(128, 2)
void attn_hmma_kernel(const unsigned char* __restrict__ mask)
{
    extern __shared__ __align__(1024) unsigned char sbuf[];
    __shared__ uint32_t smask2[2][16];

    const int tid  = threadIdx.x;
    const int wid  = tid >> 5;          // 0..3
    const int lane = tid & 31;
    const int gID  = lane >> 2;
    const int tg   = lane & 3;

    const int blk      = lane >> 3;
    const int rr       = lane & 7;
    const int aRowHalf = blk & 1;
    const int aKHalf   = blk >> 1;
    const int bNb      = blk >> 1;
    const int bKHalf   = blk & 1;

    const int vKey = lane & 15;
    const int vDh  = lane >> 4;

    const int qt = blockIdx.x;          // 0..31
    const int h  = blockIdx.y;
    const int b  = blockIdx.z;
    const int m0 = qt * 64;

    const size_t headoff = ((size_t)(b*NHEAD + h))*SEQ*DK;
    const __nv_bfloat16* Qhi = g_Qhi + headoff;
    const __nv_bfloat16* Qlo = g_Qlo + headoff;
    const __nv_bfloat16* Khi = g_Khi + headoff;
    const __nv_bfloat16* Klo = g_Klo + headoff;
    const __nv_bfloat16* Vhi = g_Vhi + headoff;
    const __nv_bfloat16* Vlo = g_Vlo + headoff;
    const unsigned char* mb = mask + (size_t)b*SEQ;

    const uint32_t sb = smem_u32(sbuf);

    const int frow = tid >> 3;          // 0..15
    const int fcol = tid & 7;           // 0..7
    uint32_t swf[4];
    #pragma unroll
    for (int i = 0; i < 4; i++)
        swf[i] = sw128((uint32_t)((frow + i*16) * 128 + fcol * 16));

    // ---- Phase 0: Q tile 64x64 bf16 (pre-scaled) -> smem -> registers
    #pragma unroll
    for (int i = 0; i < 4; i++) {
        const int f   = tid + i * 128;
        const int row = f >> 3;
        const int c   = f & 7;
        const size_t go = (size_t)(m0 + row) * DK + c * 8;
        const uint32_t sw = sw128((uint32_t)(row * 128 + c * 16));
        *(uint4*)(sbuf + sw)        = *(const uint4*)(Qhi + go);
        *(uint4*)(sbuf + 8192 + sw) = *(const uint4*)(Qlo + go);
    }
    __syncthreads();

    uint32_t qh[4][4], ql[4][4];
    #pragma unroll
    for (int ks = 0; ks < 4; ks++) {
        const uint32_t row = (uint32_t)(wid*16 + aRowHalf*8 + rr);
        const uint32_t off = sw128(row * 128 + (uint32_t)(ks*16 + aKHalf*8) * 2);
        ldmx4(qh[ks], sb + off);
        ldmx4(ql[ks], sb + 8192 + off);
    }
    __syncthreads();   // Q smem dead; overlay with K/V buffers

    float oacc[8][4];
    #pragma unroll
    for (int nb = 0; nb < 8; nb++)
        #pragma unroll
        for (int i = 0; i < 4; i++) oacc[nb][i] = 0.f;
    float lrun0 = 0.f, lrun1 = 0.f;   // per-lane partials; reduced after loop

    // ---- prologue: async-load tile 0 + mask slot 0
    {
        #pragma unroll
        for (int i = 0; i < 4; i++) {
            const size_t g = (size_t)(frow + i*16) * DK + fcol * 8;
            cp16(sb + swf[i],         Khi + g);
            cp16(sb +  8192 + swf[i], Klo + g);
            cp16(sb + 16384 + swf[i], Vhi + g);
            cp16(sb + 24576 + swf[i], Vlo + g);
        }
        CP_COMMIT();
        if (tid < 16) smask2[0][tid] = *(const uint32_t*)(mb + tid*4);
    }

    for (int t = 0; t < NT; t++) {
        const int kt = t * 64;
        const uint32_t cbuf = (uint32_t)(t & 1) * 32768;

        if (t + 1 < NT) {
            const uint32_t nbuf = (uint32_t)((t + 1) & 1) * 32768;
            const size_t base = (size_t)(kt + 64) * DK;
            #pragma unroll
            for (int i = 0; i < 4; i++) {
                const size_t g = base + (size_t)(frow + i*16) * DK + fcol * 8;
                cp16(sb + nbuf + swf[i],         Khi + g);
                cp16(sb + nbuf +  8192 + swf[i], Klo + g);
                cp16(sb + nbuf + 16384 + swf[i], Vhi + g);
                cp16(sb + nbuf + 24576 + swf[i], Vlo + g);
            }
            CP_COMMIT();
            if (tid < 16) smask2[(t+1)&1][tid] = *(const uint32_t*)(mb + kt + 64 + tid*4);
            CP_WAIT(1);          // tile t's group complete; t+1 in flight
        } else {
            CP_WAIT(0);
        }
        __syncthreads();

        const unsigned char* smk = (const unsigned char*)smask2[t & 1];

        // ---- QK^T: per ks, batch B-fragments then 3 MMA passes (dist 8)
        float sacc[8][4];
        #pragma unroll
        for (int nt = 0; nt < 8; nt++)
            #pragma unroll
            for (int i = 0; i < 4; i++) sacc[nt][i] = 0.f;

        #pragma unroll
        for (int ks = 0; ks < 4; ks++) {
            uint32_t bh[4][4], bl[4][4];
            #pragma unroll
            for (int kg = 0; kg < 4; kg++) {
                const uint32_t row = (uint32_t)(kg*16 + bNb*8 + rr);
                const uint32_t off = sw128(row * 128 + (uint32_t)(ks*16 + bKHalf*8) * 2);
                ldmx4(bh[kg], sb + cbuf + off);
                ldmx4(bl[kg], sb + cbuf + 8192 + off);
            }
            #pragma unroll
            for (int kg = 0; kg < 4; kg++)
                #pragma unroll
                for (int sub = 0; sub < 2; sub++)
                    mma_bf16(sacc[kg*2+sub], qh[ks], bh[kg][sub*2], bh[kg][sub*2+1]);
            #pragma unroll
            for (int kg = 0; kg < 4; kg++)
                #pragma unroll
                for (int sub = 0; sub < 2; sub++)
                    mma_bf16(sacc[kg*2+sub], qh[ks], bl[kg][sub*2], bl[kg][sub*2+1]);
            #pragma unroll
            for (int kg = 0; kg < 4; kg++)
                #pragma unroll
                for (int sub = 0; sub < 2; sub++)
                    mma_bf16(sacc[kg*2+sub], ql[ks], bh[kg][sub*2], bh[kg][sub*2+1]);
        }

        // ---- clip (log2 domain), mask, p=exp2(s), pack hi/lo PV fragments
        uint32_t pah[4][4], pal[4][4];
        #pragma unroll
        for (int nt = 0; nt < 8; nt++) {
            const int keyc = nt*8 + tg*2;
            const bool f0 = smk[keyc] != 0;
            const bool f1 = smk[keyc + 1] != 0;
            float s0 = fminf(fmaxf(sacc[nt][0], -CLIP_LOG2), CLIP_LOG2); if (f0) s0 = MASKED_S;
            float s1 = fminf(fmaxf(sacc[nt][1], -CLIP_LOG2), CLIP_LOG2); if (f1) s1 = MASKED_S;
            float s2 = fminf(fmaxf(sacc[nt][2], -CLIP_LOG2), CLIP_LOG2); if (f0) s2 = MASKED_S;
            float s3 = fminf(fmaxf(sacc[nt][3], -CLIP_LOG2), CLIP_LOG2); if (f1) s3 = MASKED_S;
            const float p0 = ex2(s0);
            const float p1 = ex2(s1);
            const float p2 = ex2(s2);
            const float p3 = ex2(s3);
            lrun0 += p0 + p1;
            lrun1 += p2 + p3;
            const int ks  = nt >> 1;
            const int sub = nt & 1;
            split_pack2(p0, p1, pah[ks][sub*2+0], pal[ks][sub*2+0]);
            split_pack2(p2, p3, pah[ks][sub*2+1], pal[ks][sub*2+1]);
        }

        // ---- PV: per ks, batch V-fragments then 3 MMA passes (dist 8)
        #pragma unroll
        for (int ks = 0; ks < 4; ks++) {
            uint32_t vh[4][4], vl[4][4];
            #pragma unroll
            for (int dg = 0; dg < 4; dg++) {
                const uint32_t key = (uint32_t)(ks*16 + vKey);
                const uint32_t off = sw128(key * 128 + (uint32_t)(dg*16 + vDh*8) * 2);
                ldmx4t(vh[dg], sb + cbuf + 16384 + off);
                ldmx4t(vl[dg], sb + cbuf + 24576 + off);
            }
            #pragma unroll
            for (int dg = 0; dg < 4; dg++)
                #pragma unroll
                for (int sub = 0; sub < 2; sub++)
                    mma_bf16(oacc[dg*2+sub], pah[ks], vh[dg][sub*2], vh[dg][sub*2+1]);
            #pragma unroll
            for (int dg = 0; dg < 4; dg++)
                #pragma unroll
                for (int sub = 0; sub < 2; sub++)
                    mma_bf16(oacc[dg*2+sub], pah[ks], vl[dg][sub*2], vl[dg][sub*2+1]);
            #pragma unroll
            for (int dg = 0; dg < 4; dg++)
                #pragma unroll
                for (int sub = 0; sub < 2; sub++)
                    mma_bf16(oacc[dg*2+sub], pal[ks], vh[dg][sub*2], vh[dg][sub*2+1]);
        }
        __syncthreads();   // all warps done with buf[t&1] before t+2 overwrites
    }

    // ---- deferred row-sum reduction (once, after all tiles)
    lrun0 += __shfl_xor_sync(0xffffffffu, lrun0, 1);
    lrun0 += __shfl_xor_sync(0xffffffffu, lrun0, 2);
    lrun1 += __shfl_xor_sync(0xffffffffu, lrun1, 1);
    lrun1 += __shfl_xor_sync(0xffffffffu, lrun1, 2);

    const float inv0 = 1.f / lrun0;
    const float inv1 = 1.f / lrun1;
    const int row0 = m0 + wid*16 + gID;
    const int row1 = row0 + 8;
    const size_t o0 = ((size_t)(b*SEQ + row0))*D_MODEL + h*DK;
    const size_t o1 = ((size_t)(b*SEQ + row1))*D_MODEL + h*DK;
    #pragma unroll
    for (int nb = 0; nb < 8; nb++) {
        const int col = nb*8 + tg*2;
        uint32_t H, L;
        split_pack2(oacc[nb][0]*inv0, oacc[nb][1]*inv0, H, L);
        *(uint32_t*)(g_ctxhi + o0 + col) = H;
        *(uint32_t*)(g_ctxlo + o0 + col) = L;
        split_pack2(oacc[nb][2]*inv1, oacc[nb][3]*inv1, H, L);
        *(uint32_t*)(g_ctxhi + o1 + col) = H;
        *(uint32_t*)(g_ctxlo + o1 + col) = L;
    }
}

// ---------------------------------------------------------------------------
extern "C" void kernel_launch(void* const* d_in, const int* in_sizes, int n_in,
                              void* d_out, int out_size)
{
    const float* x  = (const float*)d_in[0];
    const unsigned char* mask = (const unsigned char*)d_in[1];
    const float* Wq = (const float*)d_in[2];
    const float* bq = (const float*)d_in[3];
    const float* Wk = (const float*)d_in[4];
    const float* bk = (const float*)d_in[5];
    const float* Wv = (const float*)d_in[6];
    const float* bv = (const float*)d_in[7];
    const float* Wo = (const float*)d_in[8];
    const float* bo = (const float*)d_in[9];
    float* out = (float*)d_out;

    cudaFuncSetAttribute(attn_hmma_kernel,
                         cudaFuncAttributeMaxDynamicSharedMemorySize, ATTN_SMEM);
    cudaFuncSetAttribute(hmma_gemm_kernel<true>,
                         cudaFuncAttributeMaxDynamicSharedMemorySize, GEMM_SMEM);
    cudaFuncSetAttribute(hmma_gemm_kernel<false>,
                         cudaFuncAttributeMaxDynamicSharedMemorySize, GEMM_SMEM);

    split_x_kernel<<<M_ROWS*D_MODEL/4/256, 256>>>(x);
    split_w_kernel<<<dim3(D_MODEL*D_MODEL/4/256, 4), 256>>>(Wq, Wk, Wv, Wo);

    // 64x64 tiles: QKV grid (48, 128), O-proj grid (16, 128)
    hmma_gemm_kernel<true><<<dim3(48, M_ROWS/64), 128, GEMM_SMEM>>>(bq, bk, bv, nullptr);

    attn_hmma_kernel<<<dim3(SEQ/64, NHEAD, BATCH), 128, ATTN_SMEM>>>(mask);

    hmma_gemm_kernel<false><<<dim3(16, M_ROWS/64), 128, GEMM_SMEM>>>(bo, bo, bo, out);
}

// round 15
// speedup vs baseline: 1.0248x; 1.0115x over previous
#include <cuda_runtime.h>
#include <cuda_bf16.h>
#include <math.h>
#include <stdint.h>

#define D_MODEL 1024
#define NHEAD   16
#define DK      64
#define BATCH   4
#define SEQ     2048
#define M_ROWS  (BATCH*SEQ)   // 8192
#define HQKV    (BATCH*NHEAD*SEQ*DK)

// log2(e) folded constants
#define Q_PRESCALE 0.18033688011112042f   // 0.125 * log2(e)
#define CLIP_LOG2  72.13475204444817f     // 50 * log2(e)
#define MASKED_S   (-14427.0f)            // exp2 -> 0

// Inter-kernel interchange: bf16 hi/lo pairs (value = hi+lo, err ~2^-18 rel)
__device__ __align__(16) __nv_bfloat16 g_xhi[M_ROWS*D_MODEL];
__device__ __align__(16) __nv_bfloat16 g_xlo[M_ROWS*D_MODEL];
__device__ __align__(16) __nv_bfloat16 g_Whi[4*D_MODEL*D_MODEL];   // q,k,v,o
__device__ __align__(16) __nv_bfloat16 g_Wlo[4*D_MODEL*D_MODEL];
__device__ __align__(16) __nv_bfloat16 g_Qhi[HQKV];  // pre-scaled by 0.125*log2e
__device__ __align__(16) __nv_bfloat16 g_Qlo[HQKV];
__device__ __align__(16) __nv_bfloat16 g_Khi[HQKV];
__device__ __align__(16) __nv_bfloat16 g_Klo[HQKV];
__device__ __align__(16) __nv_bfloat16 g_Vhi[HQKV];
__device__ __align__(16) __nv_bfloat16 g_Vlo[HQKV];
__device__ __align__(16) __nv_bfloat16 g_ctxhi[M_ROWS*D_MODEL];
__device__ __align__(16) __nv_bfloat16 g_ctxlo[M_ROWS*D_MODEL];

// ---------------------------------------------------------------------------
__device__ __forceinline__ void ldmx4(uint32_t* r, uint32_t addr) {
    asm volatile("ldmatrix.sync.aligned.m8n8.x4.shared.b16 {%0,%1,%2,%3}, [%4];"
                 : "=r"(r[0]), "=r"(r[1]), "=r"(r[2]), "=r"(r[3]) : "r"(addr));
}
__device__ __forceinline__ void ldmx4t(uint32_t* r, uint32_t addr) {
    asm volatile("ldmatrix.sync.aligned.m8n8.x4.trans.shared.b16 {%0,%1,%2,%3}, [%4];"
                 : "=r"(r[0]), "=r"(r[1]), "=r"(r[2]), "=r"(r[3]) : "r"(addr));
}
__device__ __forceinline__ void mma_bf16(float* d, const uint32_t* a,
                                         uint32_t b0, uint32_t b1) {
    asm volatile(
        "mma.sync.aligned.m16n8k16.row.col.f32.bf16.bf16.f32 "
        "{%0,%1,%2,%3}, {%4,%5,%6,%7}, {%8,%9}, {%0,%1,%2,%3};"
        : "+f"(d[0]), "+f"(d[1]), "+f"(d[2]), "+f"(d[3])
        : "r"(a[0]), "r"(a[1]), "r"(a[2]), "r"(a[3]), "r"(b0), "r"(b1));
}
__device__ __forceinline__ uint32_t smem_u32(const void* p) {
    uint32_t a;
    asm("{ .reg .u64 t; cvta.to.shared.u64 t, %1; cvt.u32.u64 %0, t; }"
        : "=r"(a) : "l"(p));
    return a;
}
__device__ __forceinline__ void cp16(uint32_t saddr, const void* g) {
    asm volatile("cp.async.cg.shared.global [%0], [%1], 16;"
                 :: "r"(saddr), "l"(g) : "memory");
}
#define CP_COMMIT()   asm volatile("cp.async.commit_group;" ::: "memory")
#define CP_WAIT(n)    asm volatile("cp.async.wait_group %0;" :: "n"(n) : "memory")

__device__ __forceinline__ uint32_t sw128(uint32_t off) {
    return off ^ ((off >> 3) & 0x70);
}
__device__ __forceinline__ float ex2(float x) {
    float y;
    asm("ex2.approx.f32 %0, %1;" : "=f"(y) : "f"(x));
    return y;
}
__device__ __forceinline__ void split4(float4 v, uint2& H, uint2& L) {
    __nv_bfloat162 h0 = __floats2bfloat162_rn(v.x, v.y);
    __nv_bfloat162 h1 = __floats2bfloat162_rn(v.z, v.w);
    H.x = *reinterpret_cast<uint32_t*>(&h0);
    H.y = *reinterpret_cast<uint32_t*>(&h1);
    float rx = v.x - __uint_as_float(H.x << 16);
    float ry = v.y - __uint_as_float(H.x & 0xFFFF0000u);
    float rz = v.z - __uint_as_float(H.y << 16);
    float rw = v.w - __uint_as_float(H.y & 0xFFFF0000u);
    __nv_bfloat162 l0 = __floats2bfloat162_rn(rx, ry);
    __nv_bfloat162 l1 = __floats2bfloat162_rn(rz, rw);
    L.x = *reinterpret_cast<uint32_t*>(&l0);
    L.y = *reinterpret_cast<uint32_t*>(&l1);
}
__device__ __forceinline__ void split_pack2(float a, float b, uint32_t& H, uint32_t& L) {
    __nv_bfloat162 h2 = __floats2bfloat162_rn(a, b);
    H = *reinterpret_cast<uint32_t*>(&h2);
    float fa = __uint_as_float(H << 16);
    float fb = __uint_as_float(H & 0xFFFF0000u);
    __nv_bfloat162 l2 = __floats2bfloat162_rn(a - fa, b - fb);
    L = *reinterpret_cast<uint32_t*>(&l2);
}

// ---------------------------------------------------------------------------
// Pre-split kernels (memory-bound, one-shot)
// ---------------------------------------------------------------------------
__global__ __launch_bounds__(256) void split_x_kernel(const float* __restrict__ x) {
    const int i = blockIdx.x * 256 + threadIdx.x;
    float4 v = ((const float4*)x)[i];
    v.x += 1e-8f; v.y += 1e-8f; v.z += 1e-8f; v.w += 1e-8f;
    uint2 H, L;
    split4(v, H, L);
    ((uint2*)g_xhi)[i] = H;
    ((uint2*)g_xlo)[i] = L;
}

__global__ __launch_bounds__(256) void split_w_kernel(const float* __restrict__ W0,
                                                      const float* __restrict__ W1,
                                                      const float* __restrict__ W2,
                                                      const float* __restrict__ W3) {
    const int which = blockIdx.y;
    const float* W = which == 0 ? W0 : which == 1 ? W1 : which == 2 ? W2 : W3;
    const int i = blockIdx.x * 256 + threadIdx.x;
    float4 v = ((const float4*)W)[i];
    uint2 H, L;
    split4(v, H, L);
    const size_t o = (size_t)which * (D_MODEL*D_MODEL/4) + i;
    ((uint2*)g_Whi)[o] = H;
    ((uint2*)g_Wlo)[o] = L;
}

// ---------------------------------------------------------------------------
// HMMA GEMM v5 (unchanged from R14): 64x64 CTA tile, 128 threads, 3 CTAs/SM.
// cp.async double-buffered (prefetch-before-wait), 3-pass MMA.
// ---------------------------------------------------------------------------
#define GEMM_BUF   32768
#define GEMM_SMEM  (2*GEMM_BUF)

template<bool QKV>
__global__ __launch_bounds__(128, 3)
void hmma_gemm_kernel(const float* __restrict__ b0v,
                      const float* __restrict__ b1v,
                      const float* __restrict__ b2v,
                      float* __restrict__ outp)
{
    extern __shared__ __align__(1024) unsigned char gsm[];

    const int tid  = threadIdx.x;
    const int wid  = tid >> 5;          // 0..3
    const int lane = tid & 31;
    const int mw   = wid >> 1;          // 0..1
    const int nw   = wid & 1;           // 0..1

    const int bx    = blockIdx.x;
    const int which = QKV ? (bx >> 4) : 3;
    const int n0    = (bx & 15) * 64;
    const int m0    = blockIdx.y * 64;

    const __nv_bfloat16* Ahi = QKV ? g_xhi : g_ctxhi;
    const __nv_bfloat16* Alo = QKV ? g_xlo : g_ctxlo;
    const __nv_bfloat16* Whi = g_Whi + (size_t)which * D_MODEL * D_MODEL;
    const __nv_bfloat16* Wlo = g_Wlo + (size_t)which * D_MODEL * D_MODEL;
    const float* bias = QKV ? (which == 0 ? b0v : which == 1 ? b1v : b2v) : b0v;

    const uint32_t sb = smem_u32(gsm);

    const int blk      = lane >> 3;
    const int rr       = lane & 7;
    const int aRowHalf = blk & 1;
    const int aKHalf   = blk >> 1;
    const int bNb      = blk >> 1;
    const int bKHalf   = blk & 1;

    const int frow = tid >> 3;          // 0..15
    const int fcol = tid & 7;           // 0..7
    uint32_t swf[4];
    #pragma unroll
    for (int i = 0; i < 4; i++)
        swf[i] = sw128((uint32_t)((frow + i*16) * 128 + fcol * 16));

    float acc[2][4][4];
    #pragma unroll
    for (int i=0;i<2;i++)
        #pragma unroll
        for (int j=0;j<4;j++)
            #pragma unroll
            for (int l=0;l<4;l++) acc[i][j][l]=0.f;

    {
        #pragma unroll
        for (int i = 0; i < 4; i++) {
            const size_t ga = (size_t)(m0 + frow + i*16) * D_MODEL + fcol * 8;
            const size_t gb = (size_t)(n0 + frow + i*16) * D_MODEL + fcol * 8;
            cp16(sb + swf[i],         Ahi + ga);
            cp16(sb +  8192 + swf[i], Alo + ga);
            cp16(sb + 16384 + swf[i], Whi + gb);
            cp16(sb + 24576 + swf[i], Wlo + gb);
        }
        CP_COMMIT();
    }

    for (int chunk = 0; chunk < 16; chunk++) {
        const uint32_t cbuf = (uint32_t)(chunk & 1) * GEMM_BUF;

        if (chunk + 1 < 16) {
            const uint32_t nbuf = (uint32_t)((chunk + 1) & 1) * GEMM_BUF;
            const int k1 = (chunk + 1) * 64;
            #pragma unroll
            for (int i = 0; i < 4; i++) {
                const size_t ga = (size_t)(m0 + frow + i*16) * D_MODEL + k1 + fcol * 8;
                const size_t gb = (size_t)(n0 + frow + i*16) * D_MODEL + k1 + fcol * 8;
                cp16(sb + nbuf + swf[i],         Ahi + ga);
                cp16(sb + nbuf +  8192 + swf[i], Alo + ga);
                cp16(sb + nbuf + 16384 + swf[i], Whi + gb);
                cp16(sb + nbuf + 24576 + swf[i], Wlo + gb);
            }
            CP_COMMIT();
            CP_WAIT(1);
        } else {
            CP_WAIT(0);
        }
        __syncthreads();

        #pragma unroll
        for (int ks = 0; ks < 4; ks++) {
            uint32_t ah[2][4], al[2][4];
            #pragma unroll
            for (int mf = 0; mf < 2; mf++) {
                const uint32_t row = (uint32_t)(mw*32 + mf*16 + aRowHalf*8 + rr);
                const uint32_t off = sw128(row * 128 + (uint32_t)(ks*16 + aKHalf*8) * 2);
                ldmx4(ah[mf], sb + cbuf + off);
                ldmx4(al[mf], sb + cbuf + 8192 + off);
            }
            uint32_t bh[2][4], bl[2][4];
            #pragma unroll
            for (int pr = 0; pr < 2; pr++) {
                const uint32_t n   = (uint32_t)(nw*32 + pr*16 + bNb*8 + rr);
                const uint32_t off = sw128(n * 128 + (uint32_t)(ks*16 + bKHalf*8) * 2);
                ldmx4(bh[pr], sb + cbuf + 16384 + off);
                ldmx4(bl[pr], sb + cbuf + 24576 + off);
            }
            #pragma unroll
            for (int mf = 0; mf < 2; mf++)
                #pragma unroll
                for (int nb = 0; nb < 4; nb++)
                    mma_bf16(acc[mf][nb], ah[mf], bh[nb>>1][(nb&1)*2], bh[nb>>1][(nb&1)*2+1]);
            #pragma unroll
            for (int mf = 0; mf < 2; mf++)
                #pragma unroll
                for (int nb = 0; nb < 4; nb++)
                    mma_bf16(acc[mf][nb], ah[mf], bl[nb>>1][(nb&1)*2], bl[nb>>1][(nb&1)*2+1]);
            #pragma unroll
            for (int mf = 0; mf < 2; mf++)
                #pragma unroll
                for (int nb = 0; nb < 4; nb++)
                    mma_bf16(acc[mf][nb], al[mf], bh[nb>>1][(nb&1)*2], bh[nb>>1][(nb&1)*2+1]);
        }
        __syncthreads();   // buffer consumed before chunk+2 overwrites it
    }

    const int gID = lane >> 2;
    const int tg  = lane & 3;

    #pragma unroll
    for (int mf = 0; mf < 2; mf++) {
        #pragma unroll
        for (int nb = 0; nb < 4; nb++) {
            const int colL = nw*32 + nb*8 + tg*2;
            const float bb0 = bias[n0 + colL];
            const float bb1 = bias[n0 + colL + 1];
            #pragma unroll
            for (int half = 0; half < 2; half++) {
                const int m = m0 + mw*32 + mf*16 + half*8 + gID;
                if (QKV && which < 3) {
                    float v0 = fminf(fmaxf(acc[mf][nb][half*2+0] + bb0, -10.f), 10.f);
                    float v1 = fminf(fmaxf(acc[mf][nb][half*2+1] + bb1, -10.f), 10.f);
                    if (which == 0) { v0 *= Q_PRESCALE; v1 *= Q_PRESCALE; }
                    uint32_t H, L;
                    split_pack2(v0, v1, H, L);
                    const int b_ = m >> 11;
                    const int t  = m & (SEQ - 1);
                    const int h  = bx & 15;
                    const size_t o = (((size_t)(b_*NHEAD + h))*SEQ + t)*DK + colL;
                    __nv_bfloat16* dh = (which == 0) ? g_Qhi : (which == 1) ? g_Khi : g_Vhi;
                    __nv_bfloat16* dl = (which == 0) ? g_Qlo : (which == 1) ? g_Klo : g_Vlo;
                    *(uint32_t*)(dh + o) = H;
                    *(uint32_t*)(dl + o) = L;
                } else {
                    float2 v;
                    v.x = fminf(fmaxf(acc[mf][nb][half*2+0] + bb0, -100.f), 100.f);
                    v.y = fminf(fmaxf(acc[mf][nb][half*2+1] + bb1, -100.f), 100.f);
                    *(float2*)(outp + (size_t)m * D_MODEL + n0 + colL) = v;
                }
            }
        }
    }
}

// ---------------------------------------------------------------------------
// HMMA flash attention v9: 3-stage cp.async ring (prefetch distance 2),
// ping-pong(3) smask, early-V ks=0 fragment preload overlapping the softmax
// scalar phase, deferred row-sum reduction, full 3-pass split-bf16 PV.
// smem: 3 x 32KB ring {Khi@0 Klo@8K Vhi@16K Vlo@24K}. 2 CTAs/SM (192KB).
// ---------------------------------------------------------------------------
#define ATTN_SMEM (3*32768)
#define NT (SEQ/64)

__global__ __launch_bounds__(128, 2)
void attn_hmma_kernel(const unsigned char* __restrict__ mask)
{
    extern __shared__ __align__(1024) unsigned char sbuf[];
    __shared__ uint32_t smask3[3][16];

    const int tid  = threadIdx.x;
    const int wid  = tid >> 5;          // 0..3
    const int lane = tid & 31;
    const int gID  = lane >> 2;
    const int tg   = lane & 3;

    const int blk      = lane >> 3;
    const int rr       = lane & 7;
    const int aRowHalf = blk & 1;
    const int aKHalf   = blk >> 1;
    const int bNb      = blk >> 1;
    const int bKHalf   = blk & 1;

    const int vKey = lane & 15;
    const int vDh  = lane >> 4;

    const int qt = blockIdx.x;          // 0..31
    const int h  = blockIdx.y;
    const int b  = blockIdx.z;
    const int m0 = qt * 64;

    const size_t headoff = ((size_t)(b*NHEAD + h))*SEQ*DK;
    const __nv_bfloat16* Qhi = g_Qhi + headoff;
    const __nv_bfloat16* Qlo = g_Qlo + headoff;
    const __nv_bfloat16* Khi = g_Khi + headoff;
    const __nv_bfloat16* Klo = g_Klo + headoff;
    const __nv_bfloat16* Vhi = g_Vhi + headoff;
    const __nv_bfloat16* Vlo = g_Vlo + headoff;
    const unsigned char* mb = mask + (size_t)b*SEQ;

    const uint32_t sb = smem_u32(sbuf);

    const int frow = tid >> 3;          // 0..15
    const int fcol = tid & 7;           // 0..7
    uint32_t swf[4];
    #pragma unroll
    for (int i = 0; i < 4; i++)
        swf[i] = sw128((uint32_t)((frow + i*16) * 128 + fcol * 16));

    // ---- Phase 0: Q tile 64x64 bf16 (pre-scaled) -> smem -> registers
    #pragma unroll
    for (int i = 0; i < 4; i++) {
        const int f   = tid + i * 128;
        const int row = f >> 3;
        const int c   = f & 7;
        const size_t go = (size_t)(m0 + row) * DK + c * 8;
        const uint32_t sw = sw128((uint32_t)(row * 128 + c * 16));
        *(uint4*)(sbuf + sw)        = *(const uint4*)(Qhi + go);
        *(uint4*)(sbuf + 8192 + sw) = *(const uint4*)(Qlo + go);
    }
    __syncthreads();

    uint32_t qh[4][4], ql[4][4];
    #pragma unroll
    for (int ks = 0; ks < 4; ks++) {
        const uint32_t row = (uint32_t)(wid*16 + aRowHalf*8 + rr);
        const uint32_t off = sw128(row * 128 + (uint32_t)(ks*16 + aKHalf*8) * 2);
        ldmx4(qh[ks], sb + off);
        ldmx4(ql[ks], sb + 8192 + off);
    }
    __syncthreads();   // Q smem dead; overlay with K/V ring

    float oacc[8][4];
    #pragma unroll
    for (int nb = 0; nb < 8; nb++)
        #pragma unroll
        for (int i = 0; i < 4; i++) oacc[nb][i] = 0.f;
    float lrun0 = 0.f, lrun1 = 0.f;

    // ---- prologue: async-load tiles 0 and 1 into ring slots 0, 1
    #pragma unroll
    for (int p = 0; p < 2; p++) {
        const uint32_t pb = (uint32_t)p * 32768;
        const size_t base = (size_t)(p * 64) * DK;
        #pragma unroll
        for (int i = 0; i < 4; i++) {
            const size_t g = base + (size_t)(frow + i*16) * DK + fcol * 8;
            cp16(sb + pb + swf[i],         Khi + g);
            cp16(sb + pb +  8192 + swf[i], Klo + g);
            cp16(sb + pb + 16384 + swf[i], Vhi + g);
            cp16(sb + pb + 24576 + swf[i], Vlo + g);
        }
        CP_COMMIT();
        if (tid < 16) smask3[p][tid] = *(const uint32_t*)(mb + p*64 + tid*4);
    }

    int slot = 0;     // ring slot of tile t
    for (int t = 0; t < NT; t++) {
        const uint32_t cbuf = (uint32_t)slot * 32768;

        if (t + 2 < NT) {
            // slot of t+2 == slot of t-1: all warps finished compute(t-1) at
            // the end-of-iteration barrier of t-1, so overwrite is safe.
            const int ns = (slot + 2) % 3;
            const uint32_t nbuf = (uint32_t)ns * 32768;
            const size_t base = (size_t)((t + 2) * 64) * DK;
            #pragma unroll
            for (int i = 0; i < 4; i++) {
                const size_t g = base + (size_t)(frow + i*16) * DK + fcol * 8;
                cp16(sb + nbuf + swf[i],         Khi + g);
                cp16(sb + nbuf +  8192 + swf[i], Klo + g);
                cp16(sb + nbuf + 16384 + swf[i], Vhi + g);
                cp16(sb + nbuf + 24576 + swf[i], Vlo + g);
            }
            CP_COMMIT();
            if (tid < 16) smask3[ns][tid] = *(const uint32_t*)(mb + (t+2)*64 + tid*4);
            CP_WAIT(2);          // tile t complete; t+1, t+2 in flight
        } else if (t + 1 < NT) {
            CP_WAIT(1);
        } else {
            CP_WAIT(0);
        }
        __syncthreads();

        const unsigned char* smk = (const unsigned char*)smask3[slot];

        // ---- QK^T: per ks, batch B-fragments then 3 MMA passes (dist 8)
        float sacc[8][4];
        #pragma unroll
        for (int nt = 0; nt < 8; nt++)
            #pragma unroll
            for (int i = 0; i < 4; i++) sacc[nt][i] = 0.f;

        #pragma unroll
        for (int ks = 0; ks < 4; ks++) {
            uint32_t bh[4][4], bl[4][4];
            #pragma unroll
            for (int kg = 0; kg < 4; kg++) {
                const uint32_t row = (uint32_t)(kg*16 + bNb*8 + rr);
                const uint32_t off = sw128(row * 128 + (uint32_t)(ks*16 + bKHalf*8) * 2);
                ldmx4(bh[kg], sb + cbuf + off);
                ldmx4(bl[kg], sb + cbuf + 8192 + off);
            }
            #pragma unroll
            for (int kg = 0; kg < 4; kg++)
                #pragma unroll
                for (int sub = 0; sub < 2; sub++)
                    mma_bf16(sacc[kg*2+sub], qh[ks], bh[kg][sub*2], bh[kg][sub*2+1]);
            #pragma unroll
            for (int kg = 0; kg < 4; kg++)
                #pragma unroll
                for (int sub = 0; sub < 2; sub++)
                    mma_bf16(sacc[kg*2+sub], qh[ks], bl[kg][sub*2], bl[kg][sub*2+1]);
            #pragma unroll
            for (int kg = 0; kg < 4; kg++)
                #pragma unroll
                for (int sub = 0; sub < 2; sub++)
                    mma_bf16(sacc[kg*2+sub], ql[ks], bh[kg][sub*2], bh[kg][sub*2+1]);
        }

        // ---- early-V: issue ks=0 V-fragment loads to overlap softmax scalars
        uint32_t vh0[4][4], vl0[4][4];
        #pragma unroll
        for (int dg = 0; dg < 4; dg++) {
            const uint32_t key = (uint32_t)(0*16 + vKey);
            const uint32_t off = sw128(key * 128 + (uint32_t)(dg*16 + vDh*8) * 2);
            ldmx4t(vh0[dg], sb + cbuf + 16384 + off);
            ldmx4t(vl0[dg], sb + cbuf + 24576 + off);
        }

        // ---- clip (log2 domain), mask, p=exp2(s), pack hi/lo PV fragments
        uint32_t pah[4][4], pal[4][4];
        #pragma unroll
        for (int nt = 0; nt < 8; nt++) {
            const int keyc = nt*8 + tg*2;
            const bool f0 = smk[keyc] != 0;
            const bool f1 = smk[keyc + 1] != 0;
            float s0 = fminf(fmaxf(sacc[nt][0], -CLIP_LOG2), CLIP_LOG2); if (f0) s0 = MASKED_S;
            float s1 = fminf(fmaxf(sacc[nt][1], -CLIP_LOG2), CLIP_LOG2); if (f1) s1 = MASKED_S;
            float s2 = fminf(fmaxf(sacc[nt][2], -CLIP_LOG2), CLIP_LOG2); if (f0) s2 = MASKED_S;
            float s3 = fminf(fmaxf(sacc[nt][3], -CLIP_LOG2), CLIP_LOG2); if (f1) s3 = MASKED_S;
            const float p0 = ex2(s0);
            const float p1 = ex2(s1);
            const float p2 = ex2(s2);
            const float p3 = ex2(s3);
            lrun0 += p0 + p1;
            lrun1 += p2 + p3;
            const int ks  = nt >> 1;
            const int sub = nt & 1;
            split_pack2(p0, p1, pah[ks][sub*2+0], pal[ks][sub*2+0]);
            split_pack2(p2, p3, pah[ks][sub*2+1], pal[ks][sub*2+1]);
        }

        // ---- PV ks=0 with preloaded fragments
        #pragma unroll
        for (int dg = 0; dg < 4; dg++)
            #pragma unroll
            for (int sub = 0; sub < 2; sub++)
                mma_bf16(oacc[dg*2+sub], pah[0], vh0[dg][sub*2], vh0[dg][sub*2+1]);
        #pragma unroll
        for (int dg = 0; dg < 4; dg++)
            #pragma unroll
            for (int sub = 0; sub < 2; sub++)
                mma_bf16(oacc[dg*2+sub], pah[0], vl0[dg][sub*2], vl0[dg][sub*2+1]);
        #pragma unroll
        for (int dg = 0; dg < 4; dg++)
            #pragma unroll
            for (int sub = 0; sub < 2; sub++)
                mma_bf16(oacc[dg*2+sub], pal[0], vh0[dg][sub*2], vh0[dg][sub*2+1]);

        // ---- PV ks=1..3
        #pragma unroll
        for (int ks = 1; ks < 4; ks++) {
            uint32_t vh[4][4], vl[4][4];
            #pragma unroll
            for (int dg = 0; dg < 4; dg++) {
                const uint32_t key = (uint32_t)(ks*16 + vKey);
                const uint32_t off = sw128(key * 128 + (uint32_t)(dg*16 + vDh*8) * 2);
                ldmx4t(vh[dg], sb + cbuf + 16384 + off);
                ldmx4t(vl[dg], sb + cbuf + 24576 + off);
            }
            #pragma unroll
            for (int dg = 0; dg < 4; dg++)
                #pragma unroll
                for (int sub = 0; sub < 2; sub++)
                    mma_bf16(oacc[dg*2+sub], pah[ks], vh[dg][sub*2], vh[dg][sub*2+1]);
            #pragma unroll
            for (int dg = 0; dg < 4; dg++)
                #pragma unroll
                for (int sub = 0; sub < 2; sub++)
                    mma_bf16(oacc[dg*2+sub], pah[ks], vl[dg][sub*2], vl[dg][sub*2+1]);
            #pragma unroll
            for (int dg = 0; dg < 4; dg++)
                #pragma unroll
                for (int sub = 0; sub < 2; sub++)
                    mma_bf16(oacc[dg*2+sub], pal[ks], vh[dg][sub*2], vh[dg][sub*2+1]);
        }
        __syncthreads();   // all warps done with ring[slot] before reuse
        slot = (slot + 1) % 3;
    }

    // ---- deferred row-sum reduction (once, after all tiles)
    lrun0 += __shfl_xor_sync(0xffffffffu, lrun0, 1);
    lrun0 += __shfl_xor_sync(0xffffffffu, lrun0, 2);
    lrun1 += __shfl_xor_sync(0xffffffffu, lrun1, 1);
    lrun1 += __shfl_xor_sync(0xffffffffu, lrun1, 2);

    const float inv0 = 1.f / lrun0;
    const float inv1 = 1.f / lrun1;
    const int row0 = m0 + wid*16 + gID;
    const int row1 = row0 + 8;
    const size_t o0 = ((size_t)(b*SEQ + row0))*D_MODEL + h*DK;
    const size_t o1 = ((size_t)(b*SEQ + row1))*D_MODEL + h*DK;
    #pragma unroll
    for (int nb = 0; nb < 8; nb++) {
        const int col = nb*8 + tg*2;
        uint32_t H, L;
        split_pack2(oacc[nb][0]*inv0, oacc[nb][1]*inv0, H, L);
        *(uint32_t*)(g_ctxhi + o0 + col) = H;
        *(uint32_t*)(g_ctxlo + o0 + col) = L;
        split_pack2(oacc[nb][2]*inv1, oacc[nb][3]*inv1, H, L);
        *(uint32_t*)(g_ctxhi + o1 + col) = H;
        *(uint32_t*)(g_ctxlo + o1 + col) = L;
    }
}

// ---------------------------------------------------------------------------
extern "C" void kernel_launch(void* const* d_in, const int* in_sizes, int n_in,
                              void* d_out, int out_size)
{
    const float* x  = (const float*)d_in[0];
    const unsigned char* mask = (const unsigned char*)d_in[1];
    const float* Wq = (const float*)d_in[2];
    const float* bq = (const float*)d_in[3];
    const float* Wk = (const float*)d_in[4];
    const float* bk = (const float*)d_in[5];
    const float* Wv = (const float*)d_in[6];
    const float* bv = (const float*)d_in[7];
    const float* Wo = (const float*)d_in[8];
    const float* bo = (const float*)d_in[9];
    float* out = (float*)d_out;

    cudaFuncSetAttribute(attn_hmma_kernel,
                         cudaFuncAttributeMaxDynamicSharedMemorySize, ATTN_SMEM);
    cudaFuncSetAttribute(hmma_gemm_kernel<true>,
                         cudaFuncAttributeMaxDynamicSharedMemorySize, GEMM_SMEM);
    cudaFuncSetAttribute(hmma_gemm_kernel<false>,
                         cudaFuncAttributeMaxDynamicSharedMemorySize, GEMM_SMEM);

    split_x_kernel<<<M_ROWS*D_MODEL/4/256, 256>>>(x);
    split_w_kernel<<<dim3(D_MODEL*D_MODEL/4/256, 4), 256>>>(Wq, Wk, Wv, Wo);

    hmma_gemm_kernel<true><<<dim3(48, M_ROWS/64), 128, GEMM_SMEM>>>(bq, bk, bv, nullptr);

    attn_hmma_kernel<<<dim3(SEQ/64, NHEAD, BATCH), 128, ATTN_SMEM>>>(mask);

    hmma_gemm_kernel<false><<<dim3(16, M_ROWS/64), 128, GEMM_SMEM>>>(bo, bo, bo, out);
}